// round 1
// baseline (speedup 1.0000x reference)
#include <cuda_runtime.h>
#include <cuda_fp16.h>
#include <math.h>
#include <stdint.h>

#define S_LEN 512
#define B_SZ  64
#define H_DIM 1024
#define M_TOT (S_LEN * B_SZ)   // 32768 rows of the big GEMM
#define KDIM  H_DIM
#define NDIM  H_DIM

// ---------------- scratch (no allocations allowed) ----------------
__device__ float g_hb[B_SZ * H_DIM];      // hidden @ Wa1^T + ba   (64 x 1024)
__device__ float g_attn_raw[M_TOT];       // sum_n relu(z+hb)*Ws   (S*B)
__device__ int   g_mask_mode;             // 0=no mask, 1=byte, 2=int32, 3=float32

// ---------------- kernel 0: zero scratch + detect mask dtype ----------------
__global__ void detect_and_zero(const unsigned char* __restrict__ mask_bytes) {
    for (int i = blockIdx.x * blockDim.x + threadIdx.x; i < M_TOT;
         i += gridDim.x * blockDim.x)
        g_attn_raw[i] = 0.0f;

    if (blockIdx.x == 0) {
        __shared__ int flag[4];
        if (threadIdx.x < 4) flag[threadIdx.x] = 0;
        __syncthreads();
        // Scan first 32768 bytes (safe lower bound for any candidate dtype).
        for (int i = threadIdx.x; i < B_SZ * S_LEN; i += blockDim.x) {
            if (mask_bytes[i]) atomicOr(&flag[i & 3], 1);
        }
        __syncthreads();
        if (threadIdx.x == 0) {
            int mode;
            if (flag[1])                    mode = 1;  // 1-byte bool/uint8
            else if (flag[0])               mode = 2;  // int32 (1 -> byte%4==0)
            else if (flag[2] | flag[3])     mode = 3;  // float32 (1.0f -> bytes 2,3)
            else                            mode = 0;  // no set bits at all
            g_mask_mode = mode;
        }
    }
}

// ---------------- kernel 1: hb[b,n] = hidden[b,:] . Wa[n,0:H] + ba[n] ----------------
__global__ void hb_kernel(const float* __restrict__ hidden,
                          const float* __restrict__ Wa,
                          const float* __restrict__ ba) {
    int b    = blockIdx.x;                  // 0..63
    int warp = threadIdx.x >> 5;            // 8 warps
    int lane = threadIdx.x & 31;
    int n    = blockIdx.y * 8 + warp;       // 0..1023
    const float* hrow = hidden + b * H_DIM;
    const float* wrow = Wa + (size_t)n * (2 * H_DIM);
    float sum = 0.0f;
    #pragma unroll 8
    for (int k = lane; k < H_DIM; k += 32)
        sum += hrow[k] * wrow[k];
    #pragma unroll
    for (int o = 16; o; o >>= 1) sum += __shfl_xor_sync(0xffffffffu, sum, o);
    if (lane == 0) g_hb[b * H_DIM + n] = sum + ba[n];
}

// ---------------- kernel 2: fused GEMM (fp16 mma.sync) + relu + Ws reduction ----------------
#define BM 128
#define BN 128
#define BK 32
#define ASTRIDE 36   // half-element stride, conflict-mitigating pad

__global__ __launch_bounds__(256)
void gemm_kernel(const float* __restrict__ enc,
                 const float* __restrict__ Wa,
                 const float* __restrict__ Ws) {
    __shared__ __half As[BM * ASTRIDE];
    __shared__ __half Bs[BN * ASTRIDE];

    const int tid    = threadIdx.x;
    const int warp   = tid >> 5;
    const int lane   = tid & 31;
    const int warp_m = warp >> 2;   // 0..1  (64-row slab)
    const int warp_n = warp & 3;    // 0..3  (32-col slab)
    const int m0 = blockIdx.y * BM;
    const int n0 = blockIdx.x * BN;

    float c[4][4][4];
    #pragma unroll
    for (int a = 0; a < 4; a++)
        #pragma unroll
        for (int bq = 0; bq < 4; bq++)
            #pragma unroll
            for (int d = 0; d < 4; d++) c[a][bq][d] = 0.0f;

    // gmem loaders: 256 threads, float4 each; 32 rows x 32 cols per pass
    const int lr = tid >> 3;          // 0..31 row within pass
    const int lc = (tid & 7) * 4;     // col (floats)
    const float* Abase = enc + (size_t)m0 * KDIM;
    const float* Bbase = Wa + H_DIM;  // second half of Wa rows (encoder part)

    for (int k0 = 0; k0 < KDIM; k0 += BK) {
        #pragma unroll
        for (int rr = 0; rr < BM; rr += 32) {
            float4 v = *(const float4*)(Abase + (size_t)(rr + lr) * KDIM + k0 + lc);
            __half2* dst = (__half2*)&As[(rr + lr) * ASTRIDE + lc];
            dst[0] = __floats2half2_rn(v.x, v.y);
            dst[1] = __floats2half2_rn(v.z, v.w);
        }
        #pragma unroll
        for (int rr = 0; rr < BN; rr += 32) {
            float4 v = *(const float4*)(Bbase + (size_t)(n0 + rr + lr) * (2 * H_DIM) + k0 + lc);
            __half2* dst = (__half2*)&Bs[(rr + lr) * ASTRIDE + lc];
            dst[0] = __floats2half2_rn(v.x, v.y);
            dst[1] = __floats2half2_rn(v.z, v.w);
        }
        __syncthreads();

        #pragma unroll
        for (int kk = 0; kk < BK; kk += 16) {
            uint32_t afr[4][4], bfr[4][2];
            #pragma unroll
            for (int mf = 0; mf < 4; mf++) {
                const __half* base = &As[(warp_m * 64 + mf * 16 + (lane >> 2)) * ASTRIDE];
                const int col = (lane & 3) * 2 + kk;
                afr[mf][0] = *(const uint32_t*)(base + col);
                afr[mf][1] = *(const uint32_t*)(base + 8 * ASTRIDE + col);
                afr[mf][2] = *(const uint32_t*)(base + col + 8);
                afr[mf][3] = *(const uint32_t*)(base + 8 * ASTRIDE + col + 8);
            }
            #pragma unroll
            for (int nf = 0; nf < 4; nf++) {
                const __half* base = &Bs[(warp_n * 32 + nf * 8 + (lane >> 2)) * ASTRIDE];
                const int col = (lane & 3) * 2 + kk;
                bfr[nf][0] = *(const uint32_t*)(base + col);
                bfr[nf][1] = *(const uint32_t*)(base + col + 8);
            }
            #pragma unroll
            for (int mf = 0; mf < 4; mf++)
                #pragma unroll
                for (int nf = 0; nf < 4; nf++)
                    asm volatile(
                        "mma.sync.aligned.m16n8k16.row.col.f32.f16.f16.f32 "
                        "{%0,%1,%2,%3}, {%4,%5,%6,%7}, {%8,%9}, {%0,%1,%2,%3};\n"
                        : "+f"(c[mf][nf][0]), "+f"(c[mf][nf][1]),
                          "+f"(c[mf][nf][2]), "+f"(c[mf][nf][3])
                        : "r"(afr[mf][0]), "r"(afr[mf][1]),
                          "r"(afr[mf][2]), "r"(afr[mf][3]),
                          "r"(bfr[nf][0]), "r"(bfr[nf][1]));
        }
        __syncthreads();
    }

    // Epilogue: out_raw[m] += sum_n relu(c + hb[b,n]) * Ws[n]
    #pragma unroll
    for (int mf = 0; mf < 4; mf++) {
        #pragma unroll
        for (int i = 0; i < 2; i++) {
            const int m = m0 + warp_m * 64 + mf * 16 + (lane >> 2) + i * 8;
            const int b = m & (B_SZ - 1);          // m = s*B + b
            float part = 0.0f;
            #pragma unroll
            for (int nf = 0; nf < 4; nf++) {
                #pragma unroll
                for (int j = 0; j < 2; j++) {
                    const int n = n0 + warp_n * 32 + nf * 8 + (lane & 3) * 2 + j;
                    const float v = c[mf][nf][i * 2 + j] + g_hb[b * H_DIM + n];
                    if (v > 0.0f) part += v * Ws[n];
                }
            }
            part += __shfl_xor_sync(0xffffffffu, part, 1);
            part += __shfl_xor_sync(0xffffffffu, part, 2);
            if ((lane & 3) == 0) atomicAdd(&g_attn_raw[m], part);
        }
    }
}

// ---------------- kernel 3: logits -> masked softmax over S per batch row ----------------
__global__ void softmax_kernel(const float* __restrict__ pe,
                               const void*  __restrict__ mask,
                               float* __restrict__ out,
                               float scale) {
    const int b   = blockIdx.x;    // 0..63
    const int tid = threadIdx.x;   // 256 threads, 2 s-values each
    __shared__ float red[256];
    const int mode = g_mask_mode;

    float v[2];
    #pragma unroll
    for (int q = 0; q < 2; q++) {
        const int s   = tid + q * 256;
        const int idx = b * S_LEN + s;
        float logit = scale * g_attn_raw[s * B_SZ + b] + pe[idx];
        bool msk;
        if      (mode == 1) msk = ((const unsigned char*)mask)[idx] != 0;
        else if (mode == 2) msk = ((const int*)mask)[idx] != 0;
        else if (mode == 3) msk = ((const float*)mask)[idx] != 0.0f;
        else                msk = false;
        v[q] = msk ? -1e12f : logit;
    }

    float mx = fmaxf(v[0], v[1]);
    red[tid] = mx;
    __syncthreads();
    #pragma unroll
    for (int o = 128; o; o >>= 1) {
        if (tid < o) red[tid] = fmaxf(red[tid], red[tid + o]);
        __syncthreads();
    }
    mx = red[0];
    __syncthreads();

    const float e0 = __expf(v[0] - mx);
    const float e1 = __expf(v[1] - mx);
    red[tid] = e0 + e1;
    __syncthreads();
    #pragma unroll
    for (int o = 128; o; o >>= 1) {
        if (tid < o) red[tid] += red[tid + o];
        __syncthreads();
    }
    const float inv = 1.0f / red[0];

    out[b * S_LEN + tid]       = e0 * inv;
    out[b * S_LEN + tid + 256] = e1 * inv;
}

// ---------------- launch ----------------
extern "C" void kernel_launch(void* const* d_in, const int* in_sizes, int n_in,
                              void* d_out, int out_size) {
    const float* hidden = (const float*)d_in[0];   // (1,B,H)
    const float* enc    = (const float*)d_in[1];   // (S,B,H)
    const float* pe     = (const float*)d_in[2];   // (B,S)
    const void*  mask   =               d_in[3];   // (B,S) bool-ish
    const float* Wa     = (const float*)d_in[4];   // (H,2H)
    const float* ba     = (const float*)d_in[5];   // (H)
    const float* Ws     = (const float*)d_in[6];   // (1,H)
    float* out = (float*)d_out;                    // (B,1,S)

    const float scale = (float)(log(512.0) / sqrt(1024.0));

    detect_and_zero<<<128, 256>>>((const unsigned char*)mask);
    hb_kernel<<<dim3(B_SZ, H_DIM / 8), 256>>>(hidden, Wa, ba);
    gemm_kernel<<<dim3(NDIM / BN, M_TOT / BM), 256>>>(enc, Wa, Ws);
    softmax_kernel<<<B_SZ, 256>>>(pe, mask, out, scale);
}